// round 17
// baseline (speedup 1.0000x reference)
#include <cuda_runtime.h>
#include <cuda_bf16.h>
#include <cstdint>

#define BATCH 16
#define NTOK  4096
#define CDIM  512
#define JDIM  64
#define ROWS  (BATCH*NTOK)   // 65536
#define NCHUNK 512           // 128-row softmax chunks (32 per batch)

// ---------- scratch (device globals; no runtime allocation) ----------
__device__ __nv_bfloat16 g_Wbf[JDIM*CDIM];   // fused w1@m0, [j][c]
__device__ float         g_blog[JDIM];       // b1@m0
__device__ __nv_bfloat16 g_Mbf[CDIM*JDIM];   // fused m1@w2, [c][j]
__device__ float         g_bns[CDIM], g_bnt[CDIM];
// logits (then probabilities), bf16, CHUNK-MAJOR fragment order:
//   [row/32 block][chunk 0..7][lane 0..31][4 u32]
__device__ uint32_t      g_logbf[2048*8*32*4];           // 8 MiB
__device__ float         g_pmax[NCHUNK*JDIM], g_psum[NCHUNK*JDIM];

// ---------- helpers ----------
__device__ __forceinline__ uint32_t packbf(float x, float y) {
    __nv_bfloat162 h = __floats2bfloat162_rn(x, y);
    return *reinterpret_cast<uint32_t*>(&h);
}
__device__ __forceinline__ float2 unpackbf(uint32_t u) {
    return __bfloat1622float2(*reinterpret_cast<__nv_bfloat162*>(&u));
}
__device__ __forceinline__ float rt_bf(float x) {
    return __bfloat162float(__float2bfloat16_rn(x));
}
__device__ __forceinline__ void mma16816(float* c, const uint32_t* a, const uint32_t* b) {
    asm volatile(
        "mma.sync.aligned.m16n8k16.row.col.f32.bf16.bf16.f32 "
        "{%0,%1,%2,%3},{%4,%5,%6,%7},{%8,%9},{%0,%1,%2,%3};"
        : "+f"(c[0]), "+f"(c[1]), "+f"(c[2]), "+f"(c[3])
        : "r"(a[0]), "r"(a[1]), "r"(a[2]), "r"(a[3]), "r"(b[0]), "r"(b[1]));
}
__device__ __forceinline__ void cp_async16(uint32_t saddr, const void* gptr) {
    asm volatile("cp.async.cg.shared.global [%0], [%1], 16;" :: "r"(saddr), "l"(gptr));
}

// ---------- K0: fold weights, split-K 4x128, float4 row loads ----------
__global__ __launch_bounds__(256) void kf_fold(const float* __restrict__ w1, const float* __restrict__ b1,
                       const float* __restrict__ m0, const float* __restrict__ m1,
                       const float* __restrict__ w2, const float* __restrict__ gamma,
                       const float* __restrict__ beta, const float* __restrict__ bmean,
                       const float* __restrict__ bvar) {
    __shared__ float red[4][64];
    int blk = blockIdx.x, tid = threadIdx.x;
    int ks = tid >> 6, lx = tid & 63;

    if (blk < 512) {
        const float4* r4 = reinterpret_cast<const float4*>(w1 + (size_t)blk*CDIM + ks*128);
        const float* m0c = m0 + (size_t)(ks*128)*JDIM + lx;
        float a0=0.f, a1=0.f, a2=0.f, a3=0.f;
        #pragma unroll 8
        for (int q4 = 0; q4 < 32; q4++) {
            float4 w = r4[q4];
            int q = q4 * 4;
            a0 = fmaf(w.x, m0c[(q  )*JDIM], a0);
            a1 = fmaf(w.y, m0c[(q+1)*JDIM], a1);
            a2 = fmaf(w.z, m0c[(q+2)*JDIM], a2);
            a3 = fmaf(w.w, m0c[(q+3)*JDIM], a3);
        }
        red[ks][lx] = (a0 + a1) + (a2 + a3);
        __syncthreads();
        if (tid < 64)
            g_Wbf[tid*CDIM + blk] = __float2bfloat16_rn(
                (red[0][tid] + red[1][tid]) + (red[2][tid] + red[3][tid]));
    } else if (blk < 1024) {
        int i = blk - 512;
        int j = i >> 3, cb = i & 7;
        int c = cb*64 + lx;
        const float4* r4 = reinterpret_cast<const float4*>(m1 + (size_t)j*CDIM + ks*128);
        const float* w2c = w2 + (size_t)(ks*128)*CDIM + c;
        float a0=0.f, a1=0.f, a2=0.f, a3=0.f;
        #pragma unroll 8
        for (int q4 = 0; q4 < 32; q4++) {
            float4 m = r4[q4];
            int q = q4 * 4;
            a0 = fmaf(m.x, w2c[(q  )*CDIM], a0);
            a1 = fmaf(m.y, w2c[(q+1)*CDIM], a1);
            a2 = fmaf(m.z, w2c[(q+2)*CDIM], a2);
            a3 = fmaf(m.w, w2c[(q+3)*CDIM], a3);
        }
        red[ks][lx] = (a0 + a1) + (a2 + a3);
        __syncthreads();
        if (tid < 64)
            g_Mbf[(cb*64 + tid)*JDIM + j] = __float2bfloat16_rn(
                (red[0][tid] + red[1][tid]) + (red[2][tid] + red[3][tid]));
    } else if (blk == 1024) {
        for (int c = tid; c < CDIM; c += 256) {
            float s = gamma[c] * rsqrtf(bvar[c] + 1e-3f);
            g_bns[c] = s;
            g_bnt[c] = beta[c] - bmean[c] * s;
        }
    } else {
        const float4* r4 = reinterpret_cast<const float4*>(b1 + ks*128);
        const float* m0c = m0 + (size_t)(ks*128)*JDIM + lx;
        float a0=0.f, a1=0.f, a2=0.f, a3=0.f;
        #pragma unroll 8
        for (int q4 = 0; q4 < 32; q4++) {
            float4 w = r4[q4];
            int q = q4 * 4;
            a0 = fmaf(w.x, m0c[(q  )*JDIM], a0);
            a1 = fmaf(w.y, m0c[(q+1)*JDIM], a1);
            a2 = fmaf(w.z, m0c[(q+2)*JDIM], a2);
            a3 = fmaf(w.w, m0c[(q+3)*JDIM], a3);
        }
        red[ks][lx] = (a0 + a1) + (a2 + a3);
        __syncthreads();
        if (tid < 64)
            g_blog[tid] = (red[0][tid] + red[1][tid]) + (red[2][tid] + red[3][tid]);
    }
}

// ---------- K1: logits = inputs @ W + blog — cp.async 4-stage pipeline ----------
// grid 512, 256 thr. CTA tile: 128 rows. W resident in smem; A streamed in
// 16-col stages (128x20f padded, 4-deep ring). Warp = 16 rows (1 m16 tile).
#define KL_W_BYTES   (64*260*4)                  // 66560
#define KL_A_OFF     KL_W_BYTES
#define KL_ASTRIDE   20
#define KL_STAGE_F   (128*KL_ASTRIDE)            // 2560 floats (10240 B)
#define KL_STATS_OFF (KL_A_OFF + 4*KL_STAGE_F*4) // 107520
#define SMEM_KL      (KL_STATS_OFF + 64*4 + 8*64*4 + 64*4)  // 109824 B

__global__ __launch_bounds__(256) void kl_pipe(const float* __restrict__ in) {
    extern __shared__ __align__(16) unsigned char dyn_smem[];
    uint32_t* sw32  = reinterpret_cast<uint32_t*>(dyn_smem);              // [64][260]
    float*    sA    = reinterpret_cast<float*>(dyn_smem + KL_A_OFF);      // ring
    float*    sblog = reinterpret_cast<float*>(dyn_smem + KL_STATS_OFF);  // [64]
    float*    s_red = sblog + 64;                                         // [8][64]
    float*    s_cmx = s_red + 8*64;                                       // [64]

    int tid = threadIdx.x, cta = blockIdx.x;
    const float* gbase = in + (size_t)(cta*128)*CDIM;

    // ---- issue first 3 A stages ----
    #pragma unroll
    for (int st = 0; st < 3; st++) {
        float* dstA = sA + st*KL_STAGE_F;
        #pragma unroll
        for (int k = 0; k < 2; k++) {
            int idx = tid + k*256;               // 0..511
            int row = idx >> 2, ch = idx & 3;
            uint32_t saddr = (uint32_t)__cvta_generic_to_shared(&dstA[row*KL_ASTRIDE + ch*4]);
            cp_async16(saddr, gbase + (size_t)row*CDIM + st*16 + ch*4);
        }
        asm volatile("cp.async.commit_group;" ::: "memory");
    }

    // ---- W + blog load (covers stage-0 latency) ----
    const uint32_t* gw = reinterpret_cast<const uint32_t*>(g_Wbf); // 256 words/row
    for (int i = tid; i < 64*256; i += 256) {
        int j = i >> 8, w = i & 255;
        sw32[j*260 + w] = gw[i];
    }
    if (tid < JDIM) sblog[tid] = g_blog[tid];
    __syncthreads();

    int warp = tid >> 5, lane = tid & 31;
    int qr = lane >> 2, qc = lane & 3;
    int rw = warp * 16;                          // warp's first local row

    float acc[8][4];
    #pragma unroll
    for (int nt = 0; nt < 8; nt++) {
        float b0 = sblog[nt*8 + qc*2], b1v = sblog[nt*8 + qc*2 + 1];
        acc[nt][0] = b0; acc[nt][1] = b1v;
        acc[nt][2] = b0; acc[nt][3] = b1v;
    }

    // ---- main pipeline: 32 stages of 16 cols ----
    #pragma unroll 4
    for (int it = 0; it < 32; it++) {
        asm volatile("cp.async.wait_group 2;" ::: "memory");
        __syncthreads();

        const float* Ab = sA + (it & 3)*KL_STAGE_F;
        float4 f0 = *reinterpret_cast<const float4*>(&Ab[(rw + qr    )*KL_ASTRIDE + qc*4]);
        float4 f1 = *reinterpret_cast<const float4*>(&Ab[(rw + qr + 8)*KL_ASTRIDE + qc*4]);
        uint32_t a[4];
        a[0] = packbf(f0.x, f0.y);   // row qr,   k-low (natural cols 4qc..)
        a[1] = packbf(f1.x, f1.y);   // row qr+8, k-low
        a[2] = packbf(f0.z, f0.w);   // row qr,   k-high
        a[3] = packbf(f1.z, f1.w);   // row qr+8, k-high
        int bofs = it*8 + qc*2;
        #pragma unroll
        for (int nt = 0; nt < 8; nt++) {
            int n = nt*8 + qr;
            uint32_t b[2] = { sw32[n*260 + bofs], sw32[n*260 + bofs + 1] };
            mma16816(acc[nt], a, b);
        }
        __syncthreads();

        if (it + 3 < 32) {
            int st = it + 3;
            float* dstA = sA + (st & 3)*KL_STAGE_F;
            #pragma unroll
            for (int k = 0; k < 2; k++) {
                int idx = tid + k*256;
                int row = idx >> 2, ch = idx & 3;
                uint32_t saddr = (uint32_t)__cvta_generic_to_shared(&dstA[row*KL_ASTRIDE + ch*4]);
                cp_async16(saddr, gbase + (size_t)row*CDIM + st*16 + ch*4);
            }
        }
        asm volatile("cp.async.commit_group;" ::: "memory"); // empty groups past end
    }

    // ---- store logits, chunk-major (same g_logbf layout as before) ----
    {
        int rb = cta*4 + (warp >> 1), hh = warp & 1;
        #pragma unroll
        for (int t = 0; t < 4; t++) {
            uint4 v;
            v.x = packbf(acc[2*t  ][0], acc[2*t  ][1]);
            v.y = packbf(acc[2*t  ][2], acc[2*t  ][3]);
            v.z = packbf(acc[2*t+1][0], acc[2*t+1][1]);
            v.w = packbf(acc[2*t+1][2], acc[2*t+1][3]);
            *reinterpret_cast<uint4*>(
                g_logbf + ((size_t)rb*8 + t*2 + hh)*128 + lane*4) = v;
        }
    }

    // ---- fused softmax stats over this CTA's 128 rows (bf16-rounded) ----
    #pragma unroll
    for (int nt = 0; nt < 8; nt++) {
        #pragma unroll
        for (int h = 0; h < 2; h++) {
            float v = fmaxf(rt_bf(acc[nt][h]), rt_bf(acc[nt][h+2]));
            v = fmaxf(v, __shfl_xor_sync(0xffffffffu, v, 4));
            v = fmaxf(v, __shfl_xor_sync(0xffffffffu, v, 8));
            v = fmaxf(v, __shfl_xor_sync(0xffffffffu, v, 16));
            if (lane < 4) s_red[warp*64 + nt*8 + qc*2 + h] = v;
        }
    }
    __syncthreads();
    if (tid < 64) {
        float m = s_red[tid];
        #pragma unroll
        for (int w = 1; w < 8; w++) m = fmaxf(m, s_red[w*64 + tid]);
        s_cmx[tid] = m;
    }
    __syncthreads();
    #pragma unroll
    for (int nt = 0; nt < 8; nt++) {
        #pragma unroll
        for (int h = 0; h < 2; h++) {
            float cm = s_cmx[nt*8 + qc*2 + h];
            float v = __expf(rt_bf(acc[nt][h]) - cm) + __expf(rt_bf(acc[nt][h+2]) - cm);
            v += __shfl_xor_sync(0xffffffffu, v, 4);
            v += __shfl_xor_sync(0xffffffffu, v, 8);
            v += __shfl_xor_sync(0xffffffffu, v, 16);
            if (lane < 4) s_red[warp*64 + nt*8 + qc*2 + h] = v;
        }
    }
    __syncthreads();
    if (tid < 64) {
        float s = 0.f;
        #pragma unroll
        for (int w = 0; w < 8; w++) s += s_red[w*64 + tid];
        g_pmax[cta*JDIM + tid] = s_cmx[tid];
        g_psum[cta*JDIM + tid] = s;
    }
}

// ---------- K1b: logits -> probabilities in place (chunk-major) ----------
__global__ __launch_bounds__(256) void kp_norm() {
    __shared__ float s_tj[64];
    int tid = threadIdx.x, cta = blockIdx.x;
    int b = cta >> 4;
    if (tid < 64) {
        float gmx = -1e30f;
        float pm[32];
        #pragma unroll
        for (int ch = 0; ch < 32; ch++) {
            pm[ch] = g_pmax[(b*32 + ch)*JDIM + tid];
            gmx = fmaxf(gmx, pm[ch]);
        }
        float Z = 0.f;
        #pragma unroll
        for (int ch = 0; ch < 32; ch++)
            Z += g_psum[(b*32 + ch)*JDIM + tid] * __expf(pm[ch] - gmx);
        s_tj[tid] = -__logf(Z * (1.f + 1e-9f)) - gmx;
    }
    __syncthreads();

    int warp = tid >> 5, lane = tid & 31, qc = lane & 3;
    uint32_t* pb = g_logbf + ((size_t)(cta*8 + warp))*1024 + lane*4;

    #pragma unroll
    for (int k = 0; k < 8; k++) {
        int t = k >> 1;
        float tjA = s_tj[16*t + 2*qc],     tjB = s_tj[16*t + 2*qc + 1];
        float tjC = s_tj[16*t + 8 + 2*qc], tjD = s_tj[16*t + 8 + 2*qc + 1];
        uint4 v = *reinterpret_cast<const uint4*>(pb + k*128);
        float2 f;
        f = unpackbf(v.x); v.x = packbf(__expf(f.x + tjA), __expf(f.y + tjB));
        f = unpackbf(v.y); v.y = packbf(__expf(f.x + tjA), __expf(f.y + tjB));
        f = unpackbf(v.z); v.z = packbf(__expf(f.x + tjC), __expf(f.y + tjD));
        f = unpackbf(v.w); v.w = packbf(__expf(f.x + tjC), __expf(f.y + tjD));
        *reinterpret_cast<uint4*>(pb + k*128) = v;
    }
}

// ---------- K2: out = relu( BN( p @ M ) + inputs ) — fully async-staged ----------
#define KO_SRES_F   (64*132)                   // floats, stride 132
#define KO_LOG_OFF  (KO_SRES_F*4)              // 33792: logits 8KB (u32[2048])
#define KO_SM_OFF   (KO_LOG_OFF + 8192)        // 41984: M tile [128][36] u32
#define KO_BNS_OFF  (KO_SM_OFF + 128*36*4)     // 60416
#define SMEM_KO     (KO_BNS_OFF + 128*4*2)     // 61440 B

__global__ __launch_bounds__(256, 3) void ko_pmm(const float* __restrict__ in,
                                                 float* __restrict__ out) {
    extern __shared__ __align__(16) unsigned char ko_smem[];
    float*    sRes  = reinterpret_cast<float*>(ko_smem);                  // [64][132]
    uint32_t* sLog  = reinterpret_cast<uint32_t*>(ko_smem + KO_LOG_OFF);  // [2048]
    uint32_t* sm32  = reinterpret_cast<uint32_t*>(ko_smem + KO_SM_OFF);   // [128][36]
    float*    s_s   = reinterpret_cast<float*>(ko_smem + KO_BNS_OFF);     // [128]
    float*    s_t   = s_s + 128;                                          // [128]

    int tid = threadIdx.x;
    int mt = blockIdx.x, nt4 = blockIdx.y;
    int cbase = nt4 * 128;

    // ---- group A: M tile + logits (needed for mainloop) ----
    {
        const uint32_t* gm = reinterpret_cast<const uint32_t*>(g_Mbf) + cbase*32;
        #pragma unroll
        for (int k = 0; k < 4; k++) {
            int i = tid + k*256;            // 0..1023
            int c = i >> 3, ch = i & 7;
            uint32_t saddr = (uint32_t)__cvta_generic_to_shared(&sm32[c*36 + ch*4]);
            cp_async16(saddr, gm + c*32 + ch*4);
        }
        const uint32_t* gl = g_logbf + (size_t)(mt*2)*1024;
        #pragma unroll
        for (int k = 0; k < 2; k++) {
            int i = tid + k*256;            // 0..511
            uint32_t saddr = (uint32_t)__cvta_generic_to_shared(&sLog[i*4]);
            cp_async16(saddr, gl + i*4);
        }
        asm volatile("cp.async.commit_group;" ::: "memory");
    }
    // ---- group B: residual tile ----
    {
        const float* gsrc = in + (size_t)(mt*64)*CDIM + cbase;
        #pragma unroll
        for (int k = 0; k < 8; k++) {
            int seg = tid + k*256;           // 0..2047
            int row = seg >> 5, sc = seg & 31;
            uint32_t saddr = (uint32_t)__cvta_generic_to_shared(&sRes[row*132 + sc*4]);
            cp_async16(saddr, gsrc + (size_t)row*CDIM + sc*4);
        }
        asm volatile("cp.async.commit_group;" ::: "memory");
    }
    if (tid < 128) { s_s[tid] = g_bns[cbase + tid]; s_t[tid] = g_bnt[cbase + tid]; }

    asm volatile("cp.async.wait_group 1;" ::: "memory");
    __syncthreads();

    int warp = tid >> 5, lane = tid & 31;
    int qr = lane >> 2, qc = lane & 3;
    int wm = warp & 1, wn = warp >> 1;

    float acc[2][4][4];
    #pragma unroll
    for (int s = 0; s < 2; s++)
        #pragma unroll
        for (int nt = 0; nt < 4; nt++)
            #pragma unroll
            for (int r = 0; r < 4; r++) acc[s][nt][r] = 0.f;

    const uint32_t* lgs = sLog + wm*1024 + lane*4;

    #pragma unroll
    for (int t = 0; t < 4; t++) {
        uint32_t a[2][4];
        #pragma unroll
        for (int s = 0; s < 2; s++) {
            uint4 v = *reinterpret_cast<const uint4*>(lgs + (t*2 + s)*128);
            a[s][0] = v.x; a[s][1] = v.y; a[s][2] = v.z; a[s][3] = v.w;
        }
        int bofs = t*8 + qc;
        #pragma unroll
        for (int nt = 0; nt < 4; nt++) {
            int cl = wn*32 + nt*8 + qr;
            uint32_t bb[2] = { sm32[cl*36 + bofs], sm32[cl*36 + bofs + 4] };
            mma16816(acc[0][nt], a[0], bb);
            mma16816(acc[1][nt], a[1], bb);
        }
    }

    asm volatile("cp.async.wait_group 0;" ::: "memory");
    __syncthreads();

    int qce = qc & 1;
    #pragma unroll
    for (int p = 0; p < 2; p++) {
        int col4 = wn*32 + (2*p + qce)*8 + (qc & 2)*2;
        float4 s4 = *reinterpret_cast<const float4*>(&s_s[col4]);
        float4 t4 = *reinterpret_cast<const float4*>(&s_t[col4]);
        int col = cbase + col4;
        #pragma unroll
        for (int s = 0; s < 2; s++) {
            #pragma unroll
            for (int rh = 0; rh < 2; rh++) {
                float e0 = acc[s][2*p  ][rh*2], e1 = acc[s][2*p  ][rh*2+1];
                float o0 = acc[s][2*p+1][rh*2], o1 = acc[s][2*p+1][rh*2+1];
                float sx = qce ? e0 : o0;
                float sy = qce ? e1 : o1;
                float rx = __shfl_xor_sync(0xffffffffu, sx, 1);
                float ry = __shfl_xor_sync(0xffffffffu, sy, 1);
                float4 v;
                if (qce) { v.x = rx; v.y = ry; v.z = o0; v.w = o1; }
                else     { v.x = e0; v.y = e1; v.z = rx; v.w = ry; }
                int rl = wm*32 + qr + s*16 + rh*8;
                float4 r4 = *reinterpret_cast<const float4*>(&sRes[rl*132 + col4]);
                float4 o;
                o.x = fmaxf(fmaf(v.x, s4.x, t4.x) + r4.x, 0.f);
                o.y = fmaxf(fmaf(v.y, s4.y, t4.y) + r4.y, 0.f);
                o.z = fmaxf(fmaf(v.z, s4.z, t4.z) + r4.z, 0.f);
                o.w = fmaxf(fmaf(v.w, s4.w, t4.w) + r4.w, 0.f);
                int row = mt*64 + rl;
                *reinterpret_cast<float4*>(&out[(size_t)row*CDIM + col]) = o;
            }
        }
    }
}

// ---------- launch ----------
extern "C" void kernel_launch(void* const* d_in, const int* in_sizes, int n_in,
                              void* d_out, int out_size) {
    (void)in_sizes; (void)n_in; (void)out_size;
    const float* inputs = (const float*)d_in[0];
    const float* w1     = (const float*)d_in[1];
    const float* b1     = (const float*)d_in[2];
    const float* m0     = (const float*)d_in[3];
    const float* m1     = (const float*)d_in[4];
    const float* w2     = (const float*)d_in[5];
    const float* gamma  = (const float*)d_in[6];
    const float* beta   = (const float*)d_in[7];
    const float* bmean  = (const float*)d_in[8];
    const float* bvar   = (const float*)d_in[9];

    cudaFuncSetAttribute(kl_pipe, cudaFuncAttributeMaxDynamicSharedMemorySize,
                         SMEM_KL);
    cudaFuncSetAttribute(ko_pmm, cudaFuncAttributeMaxDynamicSharedMemorySize,
                         SMEM_KO);

    kf_fold<<<1026, 256>>>(w1, b1, m0, m1, w2, gamma, beta, bmean, bvar);
    kl_pipe<<<512, 256, SMEM_KL>>>(inputs);
    kp_norm<<<256, 256>>>();
    ko_pmm<<<dim3(ROWS / 64, 4), 256, SMEM_KO>>>(inputs, (float*)d_out);
}